// round 4
// baseline (speedup 1.0000x reference)
#include <cuda_runtime.h>
#include <math.h>
#include <stdint.h>

#define NN   8192
#define SQ   4
#define DIM  512
#define NH   4
#define DH   128
#define ET   73728
#define BOUT 128

// ---------------- scratch (device globals; no runtime alloc allowed) -------
__device__ float g_node_raw[NN * 8];
__device__ float g_node_pos[NN * DIM];
__device__ float g_X   [SQ * NN * DIM];
__device__ float g_Xout[SQ * NN * DIM];
__device__ float g_QKV [(size_t)SQ * NN * 3 * DIM];
__device__ float g_eh  [(size_t)ET * DIM];
__device__ float g_e0  [(size_t)ET * DIM];
__device__ float g_e1  [(size_t)SQ * ET * DIM];
__device__ float g_Ew1 [(size_t)ET * 2 * DIM];
__device__ float g_Ew2 [(size_t)SQ * ET * 2 * DIM];
__device__ float g_logits[SQ * ET * NH];
__device__ float g_m[SQ * NN * NH];
__device__ float g_z[SQ * NN * NH];
__device__ float g_Wpack[2 * DIM * 3 * DIM];
__device__ float g_wn2r[DIM * DIM];
__device__ float g_wp2r[DIM * DIM];
__device__ float g_WEr[2 * DIM * 2 * DIM];

// ---------------- tf32 helpers ----------------------------------------------
__device__ __forceinline__ uint32_t f2tf(float x) {
    uint32_t u; asm("cvt.rna.tf32.f32 %0, %1;" : "=r"(u) : "f"(x)); return u;
}
__device__ __forceinline__ float f2tf_f(float x) { return __uint_as_float(f2tf(x)); }

// ---------------- small utility kernels ------------------------------------
__global__ void kzero(float* __restrict__ p, size_t n) {
    size_t i = (size_t)blockIdx.x * blockDim.x + threadIdx.x;
    if (i < n) p[i] = 0.f;
}

__global__ void k_round(float* __restrict__ p, size_t n) {
    size_t i = (size_t)blockIdx.x * blockDim.x + threadIdx.x;
    if (i < n) p[i] = f2tf_f(p[i]);
}

__global__ void k_roundcopy(const float* __restrict__ s, float* __restrict__ d, size_t n) {
    size_t i = (size_t)blockIdx.x * blockDim.x + threadIdx.x;
    if (i < n) d[i] = f2tf_f(s[i]);
}

__global__ void k_selfloop(const int* __restrict__ ei, const float* __restrict__ emb) {
    int e = blockIdx.x * blockDim.x + threadIdx.x;
    if (e >= ET) return;
    int s = ei[e], d = ei[ET + e];
    if (s == d) {
        #pragma unroll
        for (int r = 0; r < 8; r++)
            atomicAdd(&g_node_raw[s * 8 + r], emb[e * 8 + r]);
    }
}

__global__ void k_mlp1(const float* __restrict__ in, const float* __restrict__ w1,
                       const float* __restrict__ b1, float* __restrict__ out, int rows) {
    long long idx = (long long)blockIdx.x * blockDim.x + threadIdx.x;
    if (idx >= (long long)rows * DIM) return;
    int n = (int)(idx >> 9), j = (int)(idx & 511);
    const float* ip = in + (long long)n * 8;
    float acc = b1[j];
    #pragma unroll
    for (int r = 0; r < 8; r++) acc = fmaf(ip[r], w1[r * DIM + j], acc);
    out[idx] = f2tf_f(fmaxf(acc, 0.f));
}

__global__ void k_add(const float* __restrict__ query, const float* __restrict__ npos,
                      float* __restrict__ X) {
    size_t idx = (size_t)blockIdx.x * blockDim.x + threadIdx.x;
    if (idx >= (size_t)SQ * NN * DIM) return;
    int j = (int)(idx & 511);
    int n = (int)((idx >> 9) % NN);
    int s = (int)(idx / ((size_t)NN * DIM));
    X[idx] = f2tf_f(query[(size_t)n * SQ * DIM + (size_t)s * DIM + j] +
                    npos[(size_t)n * DIM + j]);
}

__global__ void k_gather(const float* __restrict__ X, const int* __restrict__ mapping,
                         float* __restrict__ out) {
    int idx = blockIdx.x * blockDim.x + threadIdx.x;
    if (idx >= BOUT * SQ * DIM) return;
    int j = idx & 511;
    int s = (idx >> 9) & 3;
    int b = idx >> 11;
    out[idx] = X[((size_t)s * NN + mapping[b]) * DIM + j];
}

__global__ void k_packw(const float* __restrict__ WQ, const float* __restrict__ WK,
                        const float* __restrict__ WV) {
    int idx = blockIdx.x * blockDim.x + threadIdx.x;
    if (idx >= 2 * DIM * 3 * DIM) return;
    int j = idx % (3 * DIM);
    int k = (idx / (3 * DIM)) % DIM;
    int l = idx / (3 * DIM * DIM);
    float v;
    if (j < DIM)            v = WQ[(size_t)l * DIM * DIM + k * DIM + j];
    else if (j < 2 * DIM)   v = WK[(size_t)l * DIM * DIM + k * DIM + (j - DIM)];
    else                    v = WV[(size_t)l * DIM * DIM + k * DIM + (j - 2 * DIM)];
    g_Wpack[idx] = f2tf_f(v);
}

// ---------------- TF32 tensor-core GEMM, 128x256 tile, cp.async 3-stage -----
// C[M,N] = A[M,K] @ B[K,N] (+bias). A,B tf32-rounded fp32, row-major.
// M mult of 128, N mult of 256, K mult of 16.
#define BK      16
#define BN      256
#define STAGES  3
#define ASTR    20
#define BSTR    (BN + 8)
#define A_ELEMS (128 * ASTR)
#define B_ELEMS (BK * BSTR)
#define GEMM_SMEM ((STAGES * (A_ELEMS + B_ELEMS)) * 4)

__device__ __forceinline__ void cp16(uint32_t dst, const void* src) {
    asm volatile("cp.async.cg.shared.global [%0], [%1], 16;\n" :: "r"(dst), "l"(src));
}
__device__ __forceinline__ void cp_commit() { asm volatile("cp.async.commit_group;\n"); }
__device__ __forceinline__ void cp_wait1()  { asm volatile("cp.async.wait_group 1;\n"); }

__device__ __forceinline__ void mma_tf32(float& c0, float& c1, float& c2, float& c3,
                                         uint32_t a0, uint32_t a1, uint32_t a2, uint32_t a3,
                                         uint32_t b0, uint32_t b1) {
    asm volatile("mma.sync.aligned.m16n8k8.row.col.f32.tf32.tf32.f32 "
                 "{%0,%1,%2,%3}, {%4,%5,%6,%7}, {%8,%9}, {%0,%1,%2,%3};\n"
                 : "+f"(c0), "+f"(c1), "+f"(c2), "+f"(c3)
                 : "r"(a0), "r"(a1), "r"(a2), "r"(a3), "r"(b0), "r"(b1));
}

__global__ void __launch_bounds__(256, 1)
gemm_tf32(const float* __restrict__ A, const float* __restrict__ B,
          const float* __restrict__ bias, float* __restrict__ C,
          int M, int N, int K, int roundC) {
    extern __shared__ float sm[];
    float* Abase = sm;
    float* Bbase = sm + STAGES * A_ELEMS;

    const int tid  = threadIdx.x;
    const int lane = tid & 31;
    const int warp = tid >> 5;
    const int wm = warp & 1;      // 2 warps along M (64 rows each)
    const int wn = warp >> 1;     // 4 warps along N (64 cols each)
    const int tg = lane >> 2;
    const int tc = lane & 3;

    const long long bRow = (long long)blockIdx.y * 128;
    const long long bCol = (long long)blockIdx.x * BN;

    // cp.async mapping: A = 128x16 (2 float4/thread), B = 16x256 (4 float4/thread)
    const int arow = tid >> 2;             // 0..63 (and +64)
    const int acol = (tid & 3) * 4;
    const int brw  = tid >> 6;             // 0..3 (and +4,+8,+12)
    const int bcl  = (tid & 63) * 4;

    const float* Ag0 = A + (bRow + arow)      * (long long)K + acol;
    const float* Ag1 = A + (bRow + arow + 64) * (long long)K + acol;
    const float* Bg  = B + (long long)brw * N + bCol + bcl;

    uint32_t suA = (uint32_t)__cvta_generic_to_shared(Abase);
    uint32_t suB = (uint32_t)__cvta_generic_to_shared(Bbase);
    const uint32_t aD0 = suA + (uint32_t)(arow * ASTR + acol) * 4u;
    const uint32_t aD1 = suA + (uint32_t)((arow + 64) * ASTR + acol) * 4u;
    const uint32_t bD  = suB + (uint32_t)(brw * BSTR + bcl) * 4u;

    float acc[4][8][4];
    #pragma unroll
    for (int mt = 0; mt < 4; mt++)
        #pragma unroll
        for (int nt = 0; nt < 8; nt++)
            #pragma unroll
            for (int q = 0; q < 4; q++) acc[mt][nt][q] = 0.f;

    const int KT = K / BK;

    #pragma unroll
    for (int s = 0; s < 2; s++) {
        const int ko = s * BK;
        cp16(aD0 + (uint32_t)(s * A_ELEMS * 4), Ag0 + ko);
        cp16(aD1 + (uint32_t)(s * A_ELEMS * 4), Ag1 + ko);
        #pragma unroll
        for (int j = 0; j < 4; j++)
            cp16(bD + (uint32_t)((s * B_ELEMS + j * 4 * BSTR) * 4),
                 Bg + (long long)(ko + j * 4) * N);
        cp_commit();
    }

    for (int kt = 0; kt < KT; kt++) {
        cp_wait1();
        __syncthreads();

        if (kt + 2 < KT) {
            const int st = (kt + 2) % STAGES;
            const int ko = (kt + 2) * BK;
            cp16(aD0 + (uint32_t)(st * A_ELEMS * 4), Ag0 + ko);
            cp16(aD1 + (uint32_t)(st * A_ELEMS * 4), Ag1 + ko);
            #pragma unroll
            for (int j = 0; j < 4; j++)
                cp16(bD + (uint32_t)((st * B_ELEMS + j * 4 * BSTR) * 4),
                     Bg + (long long)(ko + j * 4) * N);
        }
        cp_commit();

        const float* Ab = Abase + (kt % STAGES) * A_ELEMS;
        const float* Bb = Bbase + (kt % STAGES) * B_ELEMS;

        #pragma unroll
        for (int kk = 0; kk < BK; kk += 8) {
            uint32_t af[4][4], bf[8][2];
            #pragma unroll
            for (int mt = 0; mt < 4; mt++) {
                int row = wm * 64 + mt * 16 + tg;
                af[mt][0] = __float_as_uint(Ab[row * ASTR + kk + tc]);
                af[mt][1] = __float_as_uint(Ab[(row + 8) * ASTR + kk + tc]);
                af[mt][2] = __float_as_uint(Ab[row * ASTR + kk + tc + 4]);
                af[mt][3] = __float_as_uint(Ab[(row + 8) * ASTR + kk + tc + 4]);
            }
            #pragma unroll
            for (int nt = 0; nt < 8; nt++) {
                int col = wn * 64 + nt * 8 + tg;
                bf[nt][0] = __float_as_uint(Bb[(kk + tc) * BSTR + col]);
                bf[nt][1] = __float_as_uint(Bb[(kk + tc + 4) * BSTR + col]);
            }
            #pragma unroll
            for (int mt = 0; mt < 4; mt++)
                #pragma unroll
                for (int nt = 0; nt < 8; nt++)
                    mma_tf32(acc[mt][nt][0], acc[mt][nt][1], acc[mt][nt][2], acc[mt][nt][3],
                             af[mt][0], af[mt][1], af[mt][2], af[mt][3],
                             bf[nt][0], bf[nt][1]);
        }
        __syncthreads();
    }

    // epilogue
    #pragma unroll
    for (int mt = 0; mt < 4; mt++) {
        #pragma unroll
        for (int nt = 0; nt < 8; nt++) {
            long long row0 = bRow + wm * 64 + mt * 16 + tg;
            long long col  = bCol + wn * 64 + nt * 8 + tc * 2;
            float b0 = 0.f, b1 = 0.f;
            if (bias) { b0 = bias[col]; b1 = bias[col + 1]; }
            float2 v0 = make_float2(acc[mt][nt][0] + b0, acc[mt][nt][1] + b1);
            float2 v1 = make_float2(acc[mt][nt][2] + b0, acc[mt][nt][3] + b1);
            if (roundC) {
                v0.x = f2tf_f(v0.x); v0.y = f2tf_f(v0.y);
                v1.x = f2tf_f(v1.x); v1.y = f2tf_f(v1.y);
            }
            *(float2*)(C + row0 * N + col)       = v0;
            *(float2*)(C + (row0 + 8) * N + col) = v1;
        }
    }
}

// ---------------- edge attention (batched over positions) ------------------
__global__ void k_edge(const float* __restrict__ QKV,
                       const int* __restrict__ src, const int* __restrict__ dst,
                       const float* __restrict__ EwEb, int sStride,
                       const float* __restrict__ aw, float* __restrict__ e_out) {
    long long w = ((long long)blockIdx.x * blockDim.x + threadIdx.x) >> 5;
    int lane = threadIdx.x & 31;
    if (w >= (long long)SQ * ET * NH) return;
    int s = (int)(w / (ET * NH));
    int r = (int)(w % (ET * NH));
    int e = r >> 2, h = r & 3;
    int sn = src[e], dn = dst[e];
    const float* qp  = QKV + ((size_t)s * NN + dn) * (3 * DIM) + h * DH;
    const float* kp  = QKV + ((size_t)s * NN + sn) * (3 * DIM) + DIM + h * DH;
    const float* ewp = EwEb + ((size_t)s * sStride + e) * (2 * DIM) + h * 256;
    float lg = 0.f;
    float vals[4];
    #pragma unroll
    for (int i = 0; i < 4; i++) {
        int dd = lane + 32 * i;
        float t  = (kp[dd] + qp[dd]) * ewp[dd];
        float ss = (t >= 0.f) ? sqrtf(t) : -sqrtf(-t);
        ss = fmaxf(ss + ewp[128 + dd], 0.f);
        vals[i] = ss;
        lg = fmaf(ss, aw[h * DH + dd], lg);
    }
    if (e_out) {
        float* op = e_out + ((size_t)s * ET + e) * DIM + h * DH;
        #pragma unroll
        for (int i = 0; i < 4; i++) op[lane + 32 * i] = f2tf_f(vals[i]);
    }
    #pragma unroll
    for (int off = 16; off; off >>= 1) lg += __shfl_xor_sync(0xffffffffu, lg, off);
    if (lane == 0) g_logits[(size_t)s * ET * NH + e * NH + h] = lg;
}

__global__ void k_initmz() {
    int i = blockIdx.x * blockDim.x + threadIdx.x;
    if (i < SQ * NN * NH) { g_m[i] = __int_as_float(0xff800000); g_z[i] = 0.f; }
}

__device__ __forceinline__ void atomicMaxF(float* addr, float val) {
    int* ia = (int*)addr;
    int old = *ia;
    while (__int_as_float(old) < val) {
        int assumed = old;
        old = atomicCAS(ia, assumed, __float_as_int(val));
        if (old == assumed) break;
    }
}

__global__ void k_max(const int* __restrict__ dst) {
    int i = blockIdx.x * blockDim.x + threadIdx.x;
    if (i >= SQ * ET * NH) return;
    int s = i / (ET * NH);
    int r = i % (ET * NH);
    int e = r >> 2, h = r & 3;
    atomicMaxF(&g_m[(s * NN + dst[e]) * NH + h], g_logits[i]);
}

__global__ void k_expsum(const int* __restrict__ dst) {
    int i = blockIdx.x * blockDim.x + threadIdx.x;
    if (i >= SQ * ET * NH) return;
    int s = i / (ET * NH);
    int r = i % (ET * NH);
    int e = r >> 2, h = r & 3;
    float wv = expf(g_logits[i] - g_m[(s * NN + dst[e]) * NH + h]);
    g_logits[i] = wv;
    atomicAdd(&g_z[(s * NN + dst[e]) * NH + h], wv);
}

__global__ void k_msg(const float* __restrict__ QKV, const int* __restrict__ src,
                      const int* __restrict__ dst, float* __restrict__ xout) {
    long long w = ((long long)blockIdx.x * blockDim.x + threadIdx.x) >> 5;
    int lane = threadIdx.x & 31;
    if (w >= (long long)SQ * ET * NH) return;
    int s = (int)(w / (ET * NH));
    int r = (int)(w % (ET * NH));
    int e = r >> 2, h = r & 3;
    int sn = src[e], dn = dst[e];
    float alpha = g_logits[(size_t)s * ET * NH + e * NH + h] /
                  (g_z[(s * NN + dn) * NH + h] + 1e-16f);
    const float* vp = QKV + ((size_t)s * NN + sn) * (3 * DIM) + 2 * DIM + h * DH;
    float* op = xout + ((size_t)s * NN + dn) * DIM + h * DH;
    #pragma unroll
    for (int i = 0; i < 4; i++) {
        int dd = lane + 32 * i;
        atomicAdd(&op[dd], vp[dd] * alpha);
    }
}

// ---------------- host orchestration ---------------------------------------
extern "C" void kernel_launch(void* const* d_in, const int* in_sizes, int n_in,
                              void* d_out, int out_size) {
    const float* query   = (const float*)d_in[0];
    const int*   ei      = (const int*)  d_in[1];
    const int*   mapping = (const int*)  d_in[2];
    const float* emb     = (const float*)d_in[3];
    const float* wn_w1 = (const float*)d_in[5];
    const float* wn_b1 = (const float*)d_in[6];
    const float* wn_w2 = (const float*)d_in[7];
    const float* wn_b2 = (const float*)d_in[8];
    const float* wp_w1 = (const float*)d_in[9];
    const float* wp_b1 = (const float*)d_in[10];
    const float* wp_w2 = (const float*)d_in[11];
    const float* wp_b2 = (const float*)d_in[12];
    const float* WQ    = (const float*)d_in[13];
    const float* WK    = (const float*)d_in[14];
    const float* WV    = (const float*)d_in[15];
    const float* WE    = (const float*)d_in[16];
    const float* bE    = (const float*)d_in[17];
    const float* Aw    = (const float*)d_in[18];
    float* out = (float*)d_out;

    float *node_raw, *node_pos, *X, *Xout, *QKV, *eh, *e0, *e1, *Ew1, *Ew2;
    float *Wpack, *wn2r, *wp2r, *WEr;
    cudaGetSymbolAddress((void**)&node_raw, g_node_raw);
    cudaGetSymbolAddress((void**)&node_pos, g_node_pos);
    cudaGetSymbolAddress((void**)&X,    g_X);
    cudaGetSymbolAddress((void**)&Xout, g_Xout);
    cudaGetSymbolAddress((void**)&QKV,  g_QKV);
    cudaGetSymbolAddress((void**)&eh,   g_eh);
    cudaGetSymbolAddress((void**)&e0,   g_e0);
    cudaGetSymbolAddress((void**)&e1,   g_e1);
    cudaGetSymbolAddress((void**)&Ew1,  g_Ew1);
    cudaGetSymbolAddress((void**)&Ew2,  g_Ew2);
    cudaGetSymbolAddress((void**)&Wpack, g_Wpack);
    cudaGetSymbolAddress((void**)&wn2r, g_wn2r);
    cudaGetSymbolAddress((void**)&wp2r, g_wp2r);
    cudaGetSymbolAddress((void**)&WEr,  g_WEr);

    static int smemSet = 0;
    if (!smemSet) {
        cudaFuncSetAttribute(gemm_tf32, cudaFuncAttributeMaxDynamicSharedMemorySize, GEMM_SMEM);
        smemSet = 1;
    }

    const int* srcp = ei;
    const int* dstp = ei + ET;
    const int T = 256;

    // ---- round weights (tiny) ----
    k_roundcopy<<<(DIM * DIM + T - 1) / T, T>>>(wn_w2, wn2r, DIM * DIM);
    k_roundcopy<<<(DIM * DIM + T - 1) / T, T>>>(wp_w2, wp2r, DIM * DIM);
    k_roundcopy<<<(2 * DIM * 2 * DIM + T - 1) / T, T>>>(WE, WEr, 2 * DIM * 2 * DIM);
    k_packw<<<(2 * DIM * 3 * DIM) / T, T>>>(WQ, WK, WV);

    // ---- position-invariant precompute ----
    kzero<<<(NN * 8 + T - 1) / T, T>>>(node_raw, NN * 8);
    k_selfloop<<<(ET + T - 1) / T, T>>>(ei, emb);
    k_mlp1<<<(NN * DIM) / T, T>>>(node_raw, wn_w1, wn_b1, X, NN);
    gemm_tf32<<<dim3(DIM / BN, NN / 128), T, GEMM_SMEM>>>(X, wn2r, wn_b2, node_pos,
                                                          NN, DIM, DIM, 0);
    k_mlp1<<<(ET * DIM) / T, T>>>(emb, wp_w1, wp_b1, eh, ET);
    gemm_tf32<<<dim3(DIM / BN, ET / 128), T, GEMM_SMEM>>>(eh, wp2r, wp_b2, e0,
                                                          ET, DIM, DIM, 1);
    gemm_tf32<<<dim3((2 * DIM) / BN, ET / 128), T, GEMM_SMEM>>>(e0, WEr, bE, Ew1,
                                                                ET, 2 * DIM, DIM, 0);

    // ---- batched positions ----
    k_add<<<(SQ * NN * DIM) / T, T>>>(query, node_pos, X);

    const long long edgeWarps = (long long)SQ * ET * NH;
    const int edgeWarpBlocks = (int)((edgeWarps * 32) / T);
    const int ehBlocks = (int)(edgeWarps / T);

    float* xin = X;
    float* xout = Xout;
    for (int l = 0; l < 2; l++) {
        const float* EwEb;
        int sStride;
        if (l == 0) { EwEb = Ew1; sStride = 0; }
        else {
            gemm_tf32<<<dim3((2 * DIM) / BN, (SQ * ET) / 128), T, GEMM_SMEM>>>(
                e1, WEr + (size_t)DIM * 2 * DIM, bE + 2 * DIM, Ew2, SQ * ET, 2 * DIM, DIM, 0);
            EwEb = Ew2; sStride = ET;
        }
        gemm_tf32<<<dim3((3 * DIM) / BN, (SQ * NN) / 128), T, GEMM_SMEM>>>(
            xin, Wpack + (size_t)l * DIM * 3 * DIM, nullptr, QKV, SQ * NN, 3 * DIM, DIM, 0);

        k_edge<<<edgeWarpBlocks, T>>>(QKV, srcp, dstp, EwEb, sStride, Aw + l * DIM,
                                      (l == 0) ? e1 : (float*)nullptr);
        k_initmz<<<(SQ * NN * NH + T - 1) / T, T>>>();
        k_max<<<ehBlocks, T>>>(dstp);
        k_expsum<<<ehBlocks, T>>>(dstp);
        kzero<<<((size_t)SQ * NN * DIM + T - 1) / T, T>>>(xout, (size_t)SQ * NN * DIM);
        k_msg<<<edgeWarpBlocks, T>>>(QKV, srcp, dstp, xout);
        if (l == 0)
            k_round<<<((size_t)SQ * NN * DIM + T - 1) / T, T>>>(xout, (size_t)SQ * NN * DIM);
        float* tmp = xin; xin = xout; xout = tmp;
    }
    k_gather<<<(BOUT * SQ * DIM) / T, T>>>(xin, mapping, out);
}

// round 6
// speedup vs baseline: 1.3242x; 1.3242x over previous
#include <cuda_runtime.h>
#include <cuda_fp16.h>
#include <math.h>
#include <stdint.h>

#define NN   8192
#define SQ   4
#define DIM  512
#define NH   4
#define DH   128
#define ET   73728
#define BOUT 128

// ---------------- scratch (device globals; no runtime alloc allowed) -------
__device__ float  g_node_raw[NN * 8];
__device__ float  g_node_pos[NN * DIM];
__device__ __half g_Xth[NN * DIM];                   // node mlp hidden (fp16)
__device__ __half g_Xh [(size_t)SQ * NN * DIM];      // layer input x (fp16)
__device__ float  g_Xout[(size_t)SQ * NN * DIM];     // attention out (fp32 atomics)
__device__ float  g_QKV [(size_t)SQ * NN * 3 * DIM];
__device__ __half g_ehh [(size_t)ET * DIM];          // edge MLP hidden (fp16)
__device__ __half g_e0h [(size_t)ET * DIM];          // e0 (fp16)
__device__ __half g_e1h [(size_t)SQ * ET * DIM];     // layer-0 e_out (fp16)
__device__ float  g_Ew1 [(size_t)ET * 2 * DIM];      // layer-0 Ew/Eb
__device__ float  g_Ew2 [(size_t)SQ * ET * 2 * DIM]; // layer-1 Ew/Eb
__device__ float  g_logits[SQ * ET * NH];
__device__ float  g_m[SQ * NN * NH];
__device__ float  g_z[SQ * NN * NH];
// K-major (N,K) fp16 weights
__device__ __half g_Wpackth[2 * 3 * DIM * DIM];      // [l][n=1536][k=512]
__device__ __half g_wn2th[DIM * DIM];
__device__ __half g_wp2th[DIM * DIM];
__device__ __half g_WEth[2 * 2 * DIM * DIM];         // [l][n=1024][k=512]

// ---------------- small utility kernels ------------------------------------
__global__ void kzero(float* __restrict__ p, size_t n) {
    size_t i = (size_t)blockIdx.x * blockDim.x + threadIdx.x;
    if (i < n) p[i] = 0.f;
}

__global__ void k_tohalf(const float* __restrict__ s, __half* __restrict__ d, size_t n) {
    size_t i = (size_t)blockIdx.x * blockDim.x + threadIdx.x;
    if (i < n) d[i] = __float2half_rn(s[i]);
}

__global__ void k_selfloop(const int* __restrict__ ei, const float* __restrict__ emb) {
    int e = blockIdx.x * blockDim.x + threadIdx.x;
    if (e >= ET) return;
    int s = ei[e], d = ei[ET + e];
    if (s == d) {
        #pragma unroll
        for (int r = 0; r < 8; r++)
            atomicAdd(&g_node_raw[s * 8 + r], emb[e * 8 + r]);
    }
}

// out[n,j] = fp16( relu( sum_r in[n,r]*w1[r,j] + b1[j] ) )
__global__ void k_mlp1h(const float* __restrict__ in, const float* __restrict__ w1,
                        const float* __restrict__ b1, __half* __restrict__ out, int rows) {
    long long idx = (long long)blockIdx.x * blockDim.x + threadIdx.x;
    if (idx >= (long long)rows * DIM) return;
    int n = (int)(idx >> 9), j = (int)(idx & 511);
    const float* ip = in + (long long)n * 8;
    float acc = b1[j];
    #pragma unroll
    for (int r = 0; r < 8; r++) acc = fmaf(ip[r], w1[r * DIM + j], acc);
    out[idx] = __float2half_rn(fmaxf(acc, 0.f));
}

// Xh[s][n][j] = fp16( query[n][s][j] + node_pos[n][j] )
__global__ void k_add(const float* __restrict__ query, const float* __restrict__ npos,
                      __half* __restrict__ X) {
    size_t idx = (size_t)blockIdx.x * blockDim.x + threadIdx.x;
    if (idx >= (size_t)SQ * NN * DIM) return;
    int j = (int)(idx & 511);
    int n = (int)((idx >> 9) % NN);
    int s = (int)(idx / ((size_t)NN * DIM));
    X[idx] = __float2half_rn(query[(size_t)n * SQ * DIM + (size_t)s * DIM + j] +
                             npos[(size_t)n * DIM + j]);
}

__global__ void k_gather(const float* __restrict__ X, const int* __restrict__ mapping,
                         float* __restrict__ out) {
    int idx = blockIdx.x * blockDim.x + threadIdx.x;
    if (idx >= BOUT * SQ * DIM) return;
    int j = idx & 511;
    int s = (idx >> 9) & 3;
    int b = idx >> 11;
    out[idx] = X[((size_t)s * NN + mapping[b]) * DIM + j];
}

// transpose + fp16: W[512][Nw] -> Wt[Nw][512]
__global__ void k_transposeTh(const float* __restrict__ W, __half* __restrict__ Wt, int Nw) {
    int idx = blockIdx.x * blockDim.x + threadIdx.x;
    if (idx >= Nw * 512) return;
    int k = idx & 511;
    int n = idx >> 9;
    Wt[idx] = __float2half_rn(W[(size_t)k * Nw + n]);
}

// fused QKV pack, transposed: Wpackth[l][n(1536)][k(512)]
__global__ void k_packwTh(const float* __restrict__ WQ, const float* __restrict__ WK,
                          const float* __restrict__ WV) {
    int idx = blockIdx.x * blockDim.x + threadIdx.x;
    if (idx >= 2 * 1536 * 512) return;
    int k = idx & 511;
    int n = (idx >> 9) % 1536;
    int l = idx / (1536 * 512);
    const float* W = (n < 512) ? WQ : ((n < 1024) ? WK : WV);
    int nn = n & 511;
    g_Wpackth[idx] = __float2half_rn(W[(size_t)l * 512 * 512 + (size_t)k * 512 + nn]);
}

// ---------------- fp16 tensor-core GEMM ------------------------------------
// C[M,N] = A[M,512] @ Bt[N,512]^T (+bias). A,Bt fp16, K-major. M,N mult of 128.
// Accumulate fp32; output fp32 (halfOut=0) or fp16 (halfOut=1).
#define BKH     32
#define KTOT    512
#define KSTEPS  (KTOT / BKH)          // 16
#define STG     3
#define STRH    40                    // halves per smem row (80B: 16B-aligned, conflict-free)
#define OP_HALVES (128 * STRH)        // per operand per stage
#define GEMM_SMEM (STG * 2 * OP_HALVES * 2)   // bytes = 61440

__device__ __forceinline__ void cp16(uint32_t dst, const void* src) {
    asm volatile("cp.async.cg.shared.global [%0], [%1], 16;\n" :: "r"(dst), "l"(src));
}
__device__ __forceinline__ void cp_commit() { asm volatile("cp.async.commit_group;\n"); }
__device__ __forceinline__ void cp_wait1()  { asm volatile("cp.async.wait_group 1;\n"); }

__device__ __forceinline__ void mma_f16(float& c0, float& c1, float& c2, float& c3,
                                        uint32_t a0, uint32_t a1, uint32_t a2, uint32_t a3,
                                        uint32_t b0, uint32_t b1) {
    asm volatile("mma.sync.aligned.m16n8k16.row.col.f32.f16.f16.f32 "
                 "{%0,%1,%2,%3}, {%4,%5,%6,%7}, {%8,%9}, {%0,%1,%2,%3};\n"
                 : "+f"(c0), "+f"(c1), "+f"(c2), "+f"(c3)
                 : "r"(a0), "r"(a1), "r"(a2), "r"(a3), "r"(b0), "r"(b1));
}

__global__ void __launch_bounds__(256, 2)
gemm_h(const __half* __restrict__ A, const __half* __restrict__ Bt,
       const float* __restrict__ bias, void* __restrict__ Cout,
       int M, int N, int halfOut) {
    extern __shared__ __half sh[];
    __half* Abase = sh;
    __half* Bbase = sh + STG * OP_HALVES;

    const int tid  = threadIdx.x;
    const int lane = tid & 31;
    const int warp = tid >> 5;
    const int wm = warp & 1;      // 2 warps along M (64 rows)
    const int wn = warp >> 1;     // 4 warps along N (32 cols)
    const int g  = lane >> 2;     // 0..7
    const int t  = lane & 3;      // 0..3

    const long long bRow = (long long)blockIdx.y * 128;
    const long long bCol = (long long)blockIdx.x * 128;

    // loader: 2 chunks (16B = 8 halves) per thread per operand per stage
    int rowL[2], cL[2];
    #pragma unroll
    for (int i = 0; i < 2; i++) {
        int ch = tid * 2 + i;       // 0..511
        rowL[i] = ch >> 2;          // 0..127
        cL[i]   = ch & 3;           // 16B chunk within 64B k-slab
    }
    const uint32_t suA = (uint32_t)__cvta_generic_to_shared(Abase);
    const uint32_t suB = (uint32_t)__cvta_generic_to_shared(Bbase);
    uint32_t aD[2], bD[2];
    #pragma unroll
    for (int i = 0; i < 2; i++) {
        aD[i] = suA + (uint32_t)(rowL[i] * STRH + cL[i] * 8) * 2u;
        bD[i] = suB + (uint32_t)(rowL[i] * STRH + cL[i] * 8) * 2u;
    }
    const __half* Ag[2];
    const __half* Bg[2];
    #pragma unroll
    for (int i = 0; i < 2; i++) {
        Ag[i] = A  + (bRow + rowL[i]) * (long long)KTOT + cL[i] * 8;
        Bg[i] = Bt + (bCol + rowL[i]) * (long long)KTOT + cL[i] * 8;
    }

    float acc[4][4][4];
    #pragma unroll
    for (int mt = 0; mt < 4; mt++)
        #pragma unroll
        for (int nt = 0; nt < 4; nt++)
            #pragma unroll
            for (int q = 0; q < 4; q++) acc[mt][nt][q] = 0.f;

    // prologue: stages 0,1
    #pragma unroll
    for (int s = 0; s < 2; s++) {
        #pragma unroll
        for (int i = 0; i < 2; i++) {
            cp16(aD[i] + (uint32_t)(s * OP_HALVES * 2), Ag[i] + s * BKH);
            cp16(bD[i] + (uint32_t)(s * OP_HALVES * 2), Bg[i] + s * BKH);
        }
        cp_commit();
    }

    for (int kt = 0; kt < KSTEPS; kt++) {
        cp_wait1();
        __syncthreads();

        if (kt + 2 < KSTEPS) {
            const int st = (kt + 2) % STG;
            #pragma unroll
            for (int i = 0; i < 2; i++) {
                cp16(aD[i] + (uint32_t)(st * OP_HALVES * 2), Ag[i] + (kt + 2) * BKH);
                cp16(bD[i] + (uint32_t)(st * OP_HALVES * 2), Bg[i] + (kt + 2) * BKH);
            }
        }
        cp_commit();

        const __half* Ab = Abase + (kt % STG) * OP_HALVES;
        const __half* Bb = Bbase + (kt % STG) * OP_HALVES;

        #pragma unroll
        for (int kk = 0; kk < BKH; kk += 16) {
            uint32_t af[4][4], bf[4][2];
            #pragma unroll
            for (int mt = 0; mt < 4; mt++) {
                int row = wm * 64 + mt * 16 + g;
                af[mt][0] = *(const uint32_t*)(Ab + row * STRH + kk + 2 * t);
                af[mt][1] = *(const uint32_t*)(Ab + (row + 8) * STRH + kk + 2 * t);
                af[mt][2] = *(const uint32_t*)(Ab + row * STRH + kk + 2 * t + 8);
                af[mt][3] = *(const uint32_t*)(Ab + (row + 8) * STRH + kk + 2 * t + 8);
            }
            #pragma unroll
            for (int nt = 0; nt < 4; nt++) {
                int col = wn * 32 + nt * 8 + g;
                bf[nt][0] = *(const uint32_t*)(Bb + col * STRH + kk + 2 * t);
                bf[nt][1] = *(const uint32_t*)(Bb + col * STRH + kk + 2 * t + 8);
            }
            #pragma unroll
            for (int mt = 0; mt < 4; mt++)
                #pragma unroll
                for (int nt = 0; nt < 4; nt++)
                    mma_f16(acc[mt][nt][0], acc[mt][nt][1], acc[mt][nt][2], acc[mt][nt][3],
                            af[mt][0], af[mt][1], af[mt][2], af[mt][3],
                            bf[nt][0], bf[nt][1]);
        }
        __syncthreads();
    }

    // epilogue
    #pragma unroll
    for (int mt = 0; mt < 4; mt++) {
        #pragma unroll
        for (int nt = 0; nt < 4; nt++) {
            long long row0 = bRow + wm * 64 + mt * 16 + g;
            long long col  = bCol + wn * 32 + nt * 8 + t * 2;
            float b0 = 0.f, b1 = 0.f;
            if (bias) { b0 = bias[col]; b1 = bias[col + 1]; }
            float v00 = acc[mt][nt][0] + b0, v01 = acc[mt][nt][1] + b1;
            float v10 = acc[mt][nt][2] + b0, v11 = acc[mt][nt][3] + b1;
            if (halfOut) {
                __half2* C = (__half2*)Cout;
                C[(row0 * N + col) >> 1]       = __floats2half2_rn(v00, v01);
                C[((row0 + 8) * N + col) >> 1] = __floats2half2_rn(v10, v11);
            } else {
                float* C = (float*)Cout;
                *(float2*)(C + row0 * N + col)       = make_float2(v00, v01);
                *(float2*)(C + (row0 + 8) * N + col) = make_float2(v10, v11);
            }
        }
    }
}

// ---------------- edge attention (batched over positions) ------------------
__global__ void k_edge(const float* __restrict__ QKV,
                       const int* __restrict__ src, const int* __restrict__ dst,
                       const float* __restrict__ EwEb, int sStride,
                       const float* __restrict__ aw, __half* __restrict__ e_out) {
    long long w = ((long long)blockIdx.x * blockDim.x + threadIdx.x) >> 5;
    int lane = threadIdx.x & 31;
    if (w >= (long long)SQ * ET * NH) return;
    int s = (int)(w / (ET * NH));
    int r = (int)(w % (ET * NH));
    int e = r >> 2, h = r & 3;
    int sn = src[e], dn = dst[e];
    const float* qp  = QKV + ((size_t)s * NN + dn) * (3 * DIM) + h * DH;
    const float* kp  = QKV + ((size_t)s * NN + sn) * (3 * DIM) + DIM + h * DH;
    const float* ewp = EwEb + ((size_t)s * sStride + e) * (2 * DIM) + h * 256;
    float lg = 0.f;
    float vals[4];
    #pragma unroll
    for (int i = 0; i < 4; i++) {
        int dd = lane + 32 * i;
        float tv = (kp[dd] + qp[dd]) * ewp[dd];
        float ss = (tv >= 0.f) ? sqrtf(tv) : -sqrtf(-tv);   // signed sqrt
        ss = fmaxf(ss + ewp[128 + dd], 0.f);
        vals[i] = ss;
        lg = fmaf(ss, aw[h * DH + dd], lg);
    }
    if (e_out) {
        __half* op = e_out + ((size_t)s * ET + e) * DIM + h * DH;
        #pragma unroll
        for (int i = 0; i < 4; i++) op[lane + 32 * i] = __float2half_rn(vals[i]);
    }
    #pragma unroll
    for (int off = 16; off; off >>= 1) lg += __shfl_xor_sync(0xffffffffu, lg, off);
    if (lane == 0) g_logits[(size_t)s * ET * NH + e * NH + h] = lg;
}

__global__ void k_initmz() {
    int i = blockIdx.x * blockDim.x + threadIdx.x;
    if (i < SQ * NN * NH) { g_m[i] = __int_as_float(0xff800000); g_z[i] = 0.f; }
}

__device__ __forceinline__ void atomicMaxF(float* addr, float val) {
    int* ia = (int*)addr;
    int old = *ia;
    while (__int_as_float(old) < val) {
        int assumed = old;
        old = atomicCAS(ia, assumed, __float_as_int(val));
        if (old == assumed) break;
    }
}

__global__ void k_max(const int* __restrict__ dst) {
    int i = blockIdx.x * blockDim.x + threadIdx.x;
    if (i >= SQ * ET * NH) return;
    int s = i / (ET * NH);
    int r = i % (ET * NH);
    int e = r >> 2, h = r & 3;
    atomicMaxF(&g_m[(s * NN + dst[e]) * NH + h], g_logits[i]);
}

__global__ void k_expsum(const int* __restrict__ dst) {
    int i = blockIdx.x * blockDim.x + threadIdx.x;
    if (i >= SQ * ET * NH) return;
    int s = i / (ET * NH);
    int r = i % (ET * NH);
    int e = r >> 2, h = r & 3;
    float wv = expf(g_logits[i] - g_m[(s * NN + dst[e]) * NH + h]);
    g_logits[i] = wv;
    atomicAdd(&g_z[(s * NN + dst[e]) * NH + h], wv);
}

__global__ void k_msg(const float* __restrict__ QKV, const int* __restrict__ src,
                      const int* __restrict__ dst, float* __restrict__ xout) {
    long long w = ((long long)blockIdx.x * blockDim.x + threadIdx.x) >> 5;
    int lane = threadIdx.x & 31;
    if (w >= (long long)SQ * ET * NH) return;
    int s = (int)(w / (ET * NH));
    int r = (int)(w % (ET * NH));
    int e = r >> 2, h = r & 3;
    int sn = src[e], dn = dst[e];
    float alpha = g_logits[(size_t)s * ET * NH + e * NH + h] /
                  (g_z[(s * NN + dn) * NH + h] + 1e-16f);
    const float* vp = QKV + ((size_t)s * NN + sn) * (3 * DIM) + 2 * DIM + h * DH;
    float* op = xout + ((size_t)s * NN + dn) * DIM + h * DH;
    #pragma unroll
    for (int i = 0; i < 4; i++) {
        int dd = lane + 32 * i;
        atomicAdd(&op[dd], vp[dd] * alpha);
    }
}

// ---------------- host orchestration ---------------------------------------
extern "C" void kernel_launch(void* const* d_in, const int* in_sizes, int n_in,
                              void* d_out, int out_size) {
    const float* query   = (const float*)d_in[0];
    const int*   ei      = (const int*)  d_in[1];
    const int*   mapping = (const int*)  d_in[2];
    const float* emb     = (const float*)d_in[3];
    const float* wn_w1 = (const float*)d_in[5];
    const float* wn_b1 = (const float*)d_in[6];
    const float* wn_w2 = (const float*)d_in[7];
    const float* wn_b2 = (const float*)d_in[8];
    const float* wp_w1 = (const float*)d_in[9];
    const float* wp_b1 = (const float*)d_in[10];
    const float* wp_w2 = (const float*)d_in[11];
    const float* wp_b2 = (const float*)d_in[12];
    const float* WQ    = (const float*)d_in[13];
    const float* WK    = (const float*)d_in[14];
    const float* WV    = (const float*)d_in[15];
    const float* WE    = (const float*)d_in[16];
    const float* bE    = (const float*)d_in[17];
    const float* Aw    = (const float*)d_in[18];
    float* out = (float*)d_out;

    float  *node_raw, *node_pos, *Xout, *QKV, *Ew1, *Ew2;
    __half *Xth, *Xh, *ehh, *e0h, *e1h, *Wpackth, *wn2th, *wp2th, *WEth;
    cudaGetSymbolAddress((void**)&node_raw, g_node_raw);
    cudaGetSymbolAddress((void**)&node_pos, g_node_pos);
    cudaGetSymbolAddress((void**)&Xth,  g_Xth);
    cudaGetSymbolAddress((void**)&Xh,   g_Xh);
    cudaGetSymbolAddress((void**)&Xout, g_Xout);
    cudaGetSymbolAddress((void**)&QKV,  g_QKV);
    cudaGetSymbolAddress((void**)&ehh,  g_ehh);
    cudaGetSymbolAddress((void**)&e0h,  g_e0h);
    cudaGetSymbolAddress((void**)&e1h,  g_e1h);
    cudaGetSymbolAddress((void**)&Ew1,  g_Ew1);
    cudaGetSymbolAddress((void**)&Ew2,  g_Ew2);
    cudaGetSymbolAddress((void**)&Wpackth, g_Wpackth);
    cudaGetSymbolAddress((void**)&wn2th, g_wn2th);
    cudaGetSymbolAddress((void**)&wp2th, g_wp2th);
    cudaGetSymbolAddress((void**)&WEth,  g_WEth);

    cudaFuncSetAttribute(gemm_h, cudaFuncAttributeMaxDynamicSharedMemorySize, GEMM_SMEM);

    const int* srcp = ei;
    const int* dstp = ei + ET;
    const int T = 256;

    // ---- fp16 weight packs (tiny) ----
    k_transposeTh<<<(512 * 512) / T, T>>>(wn_w2, wn2th, 512);
    k_transposeTh<<<(512 * 512) / T, T>>>(wp_w2, wp2th, 512);
    k_transposeTh<<<(1024 * 512) / T, T>>>(WE, WEth, 1024);
    k_transposeTh<<<(1024 * 512) / T, T>>>(WE + 512 * 1024, WEth + 1024 * 512, 1024);
    k_packwTh<<<(2 * 1536 * 512) / T, T>>>(WQ, WK, WV);

    // ---- position-invariant precompute ----
    kzero<<<(NN * 8 + T - 1) / T, T>>>(node_raw, NN * 8);
    k_selfloop<<<(ET + T - 1) / T, T>>>(ei, emb);
    k_mlp1h<<<(NN * DIM) / T, T>>>(node_raw, wn_w1, wn_b1, Xth, NN);
    gemm_h<<<dim3(DIM / 128, NN / 128), T, GEMM_SMEM>>>(Xth, wn2th, wn_b2, node_pos,
                                                        NN, DIM, 0);
    k_mlp1h<<<(ET * DIM) / T, T>>>(emb, wp_w1, wp_b1, ehh, ET);
    gemm_h<<<dim3(DIM / 128, ET / 128), T, GEMM_SMEM>>>(ehh, wp2th, wp_b2, e0h,
                                                        ET, DIM, 1);
    gemm_h<<<dim3((2 * DIM) / 128, ET / 128), T, GEMM_SMEM>>>(e0h, WEth, bE, Ew1,
                                                              ET, 2 * DIM, 0);

    // ---- batched positions ----
    k_add<<<(SQ * NN * DIM) / T, T>>>(query, node_pos, Xh);

    const long long edgeWarps = (long long)SQ * ET * NH;
    const int edgeWarpBlocks = (int)((edgeWarps * 32) / T);
    const int ehBlocks = (int)(edgeWarps / T);

    for (int l = 0; l < 2; l++) {
        const float* EwEb;
        int sStride;
        if (l == 0) { EwEb = Ew1; sStride = 0; }
        else {
            gemm_h<<<dim3((2 * DIM) / 128, (SQ * ET) / 128), T, GEMM_SMEM>>>(
                e1h, WEth + 1024 * 512, bE + 2 * DIM, Ew2, SQ * ET, 2 * DIM, 0);
            EwEb = Ew2; sStride = ET;
        }
        gemm_h<<<dim3((3 * DIM) / 128, (SQ * NN) / 128), T, GEMM_SMEM>>>(
            Xh, Wpackth + (size_t)l * 1536 * 512, nullptr, QKV, SQ * NN, 3 * DIM, 0);

        k_edge<<<edgeWarpBlocks, T>>>(QKV, srcp, dstp, EwEb, sStride, Aw + l * DIM,
                                      (l == 0) ? e1h : (__half*)nullptr);
        k_initmz<<<(SQ * NN * NH + T - 1) / T, T>>>();
        k_max<<<ehBlocks, T>>>(dstp);
        k_expsum<<<ehBlocks, T>>>(dstp);
        kzero<<<((size_t)SQ * NN * DIM + T - 1) / T, T>>>(Xout, (size_t)SQ * NN * DIM);
        k_msg<<<edgeWarpBlocks, T>>>(QKV, srcp, dstp, Xout);
        if (l == 0)
            k_tohalf<<<((size_t)SQ * NN * DIM + T - 1) / T, T>>>(Xout, Xh,
                                                                 (size_t)SQ * NN * DIM);
    }
    k_gather<<<(BOUT * SQ * DIM) / T, T>>>(Xout, mapping, out);
}

// round 7
// speedup vs baseline: 1.3847x; 1.0457x over previous
#include <cuda_runtime.h>
#include <cuda_fp16.h>
#include <math.h>
#include <stdint.h>

#define NN   8192
#define SQ   4
#define DIM  512
#define NH   4
#define DH   128
#define ET   73728
#define BOUT 128

// ---------------- scratch (device globals; no runtime alloc allowed) -------
__device__ float  g_node_raw[NN * 8];
__device__ float  g_node_pos[NN * DIM];
__device__ __half g_Xth[NN * DIM];                   // node mlp hidden (fp16)
__device__ __half g_Xh [(size_t)SQ * NN * DIM];      // layer input x (fp16)
__device__ float  g_Xout[(size_t)SQ * NN * DIM];     // attention out (fp32 atomics)
__device__ __half g_QKVh[(size_t)SQ * NN * 3 * DIM]; // fused QKV (fp16)
__device__ __half g_ehh [(size_t)ET * DIM];          // edge MLP hidden (fp16)
__device__ __half g_e0h [(size_t)ET * DIM];          // e0 (fp16)
__device__ __half g_e1h [(size_t)SQ * ET * DIM];     // layer-0 e_out (fp16)
__device__ __half g_Ew1h[(size_t)ET * 2 * DIM];      // layer-0 Ew/Eb (fp16)
__device__ __half g_Ew2h[(size_t)SQ * ET * 2 * DIM]; // layer-1 Ew/Eb (fp16)
__device__ float  g_logits[SQ * ET * NH];
__device__ float  g_m[SQ * NN * NH];
__device__ float  g_z[SQ * NN * NH];
// K-major (N,K) fp16 weights
__device__ __half g_Wpackth[2 * 3 * DIM * DIM];      // [l][n=1536][k=512]
__device__ __half g_wn2th[DIM * DIM];
__device__ __half g_wp2th[DIM * DIM];
__device__ __half g_WEth[2 * 2 * DIM * DIM];         // [l][n=1024][k=512]

// ---------------- small utility kernels ------------------------------------
__global__ void kzero(float* __restrict__ p, size_t n) {
    size_t i = (size_t)blockIdx.x * blockDim.x + threadIdx.x;
    if (i < n) p[i] = 0.f;
}

__global__ void k_tohalf(const float* __restrict__ s, __half* __restrict__ d, size_t n) {
    size_t i = (size_t)blockIdx.x * blockDim.x + threadIdx.x;
    if (i < n) d[i] = __float2half_rn(s[i]);
}

__global__ void k_selfloop(const int* __restrict__ ei, const float* __restrict__ emb) {
    int e = blockIdx.x * blockDim.x + threadIdx.x;
    if (e >= ET) return;
    int s = ei[e], d = ei[ET + e];
    if (s == d) {
        #pragma unroll
        for (int r = 0; r < 8; r++)
            atomicAdd(&g_node_raw[s * 8 + r], emb[e * 8 + r]);
    }
}

// out[n,j] = fp16( relu( sum_r in[n,r]*w1[r,j] + b1[j] ) )
__global__ void k_mlp1h(const float* __restrict__ in, const float* __restrict__ w1,
                        const float* __restrict__ b1, __half* __restrict__ out, int rows) {
    long long idx = (long long)blockIdx.x * blockDim.x + threadIdx.x;
    if (idx >= (long long)rows * DIM) return;
    int n = (int)(idx >> 9), j = (int)(idx & 511);
    const float* ip = in + (long long)n * 8;
    float acc = b1[j];
    #pragma unroll
    for (int r = 0; r < 8; r++) acc = fmaf(ip[r], w1[r * DIM + j], acc);
    out[idx] = __float2half_rn(fmaxf(acc, 0.f));
}

// Xh[s][n][j] = fp16( query[n][s][j] + node_pos[n][j] )
__global__ void k_add(const float* __restrict__ query, const float* __restrict__ npos,
                      __half* __restrict__ X) {
    size_t idx = (size_t)blockIdx.x * blockDim.x + threadIdx.x;
    if (idx >= (size_t)SQ * NN * DIM) return;
    int j = (int)(idx & 511);
    int n = (int)((idx >> 9) % NN);
    int s = (int)(idx / ((size_t)NN * DIM));
    X[idx] = __float2half_rn(query[(size_t)n * SQ * DIM + (size_t)s * DIM + j] +
                             npos[(size_t)n * DIM + j]);
}

__global__ void k_gather(const float* __restrict__ X, const int* __restrict__ mapping,
                         float* __restrict__ out) {
    int idx = blockIdx.x * blockDim.x + threadIdx.x;
    if (idx >= BOUT * SQ * DIM) return;
    int j = idx & 511;
    int s = (idx >> 9) & 3;
    int b = idx >> 11;
    out[idx] = X[((size_t)s * NN + mapping[b]) * DIM + j];
}

// transpose + fp16: W[512][Nw] -> Wt[Nw][512]
__global__ void k_transposeTh(const float* __restrict__ W, __half* __restrict__ Wt, int Nw) {
    int idx = blockIdx.x * blockDim.x + threadIdx.x;
    if (idx >= Nw * 512) return;
    int k = idx & 511;
    int n = idx >> 9;
    Wt[idx] = __float2half_rn(W[(size_t)k * Nw + n]);
}

// fused QKV pack, transposed: Wpackth[l][n(1536)][k(512)]
__global__ void k_packwTh(const float* __restrict__ WQ, const float* __restrict__ WK,
                          const float* __restrict__ WV) {
    int idx = blockIdx.x * blockDim.x + threadIdx.x;
    if (idx >= 2 * 1536 * 512) return;
    int k = idx & 511;
    int n = (idx >> 9) % 1536;
    int l = idx / (1536 * 512);
    const float* W = (n < 512) ? WQ : ((n < 1024) ? WK : WV);
    int nn = n & 511;
    g_Wpackth[idx] = __float2half_rn(W[(size_t)l * 512 * 512 + (size_t)k * 512 + nn]);
}

// ---------------- fp16 tensor-core GEMM ------------------------------------
// C[M,N] = A[M,512] @ Bt[N,512]^T (+bias). A,Bt fp16, K-major. M,N mult of 128.
#define BKH     32
#define KTOT    512
#define KSTEPS  (KTOT / BKH)          // 16
#define STG     3
#define STRH    40
#define OP_HALVES (128 * STRH)
#define GEMM_SMEM (STG * 2 * OP_HALVES * 2)

__device__ __forceinline__ void cp16(uint32_t dst, const void* src) {
    asm volatile("cp.async.cg.shared.global [%0], [%1], 16;\n" :: "r"(dst), "l"(src));
}
__device__ __forceinline__ void cp_commit() { asm volatile("cp.async.commit_group;\n"); }
__device__ __forceinline__ void cp_wait1()  { asm volatile("cp.async.wait_group 1;\n"); }

__device__ __forceinline__ void mma_f16(float& c0, float& c1, float& c2, float& c3,
                                        uint32_t a0, uint32_t a1, uint32_t a2, uint32_t a3,
                                        uint32_t b0, uint32_t b1) {
    asm volatile("mma.sync.aligned.m16n8k16.row.col.f32.f16.f16.f32 "
                 "{%0,%1,%2,%3}, {%4,%5,%6,%7}, {%8,%9}, {%0,%1,%2,%3};\n"
                 : "+f"(c0), "+f"(c1), "+f"(c2), "+f"(c3)
                 : "r"(a0), "r"(a1), "r"(a2), "r"(a3), "r"(b0), "r"(b1));
}

__global__ void __launch_bounds__(256, 2)
gemm_h(const __half* __restrict__ A, const __half* __restrict__ Bt,
       const float* __restrict__ bias, void* __restrict__ Cout,
       int M, int N, int halfOut) {
    extern __shared__ __half sh[];
    __half* Abase = sh;
    __half* Bbase = sh + STG * OP_HALVES;

    const int tid  = threadIdx.x;
    const int lane = tid & 31;
    const int warp = tid >> 5;
    const int wm = warp & 1;
    const int wn = warp >> 1;
    const int g  = lane >> 2;
    const int t  = lane & 3;

    const long long bRow = (long long)blockIdx.y * 128;
    const long long bCol = (long long)blockIdx.x * 128;

    int rowL[2], cL[2];
    #pragma unroll
    for (int i = 0; i < 2; i++) {
        int ch = tid * 2 + i;
        rowL[i] = ch >> 2;
        cL[i]   = ch & 3;
    }
    const uint32_t suA = (uint32_t)__cvta_generic_to_shared(Abase);
    const uint32_t suB = (uint32_t)__cvta_generic_to_shared(Bbase);
    uint32_t aD[2], bD[2];
    #pragma unroll
    for (int i = 0; i < 2; i++) {
        aD[i] = suA + (uint32_t)(rowL[i] * STRH + cL[i] * 8) * 2u;
        bD[i] = suB + (uint32_t)(rowL[i] * STRH + cL[i] * 8) * 2u;
    }
    const __half* Ag[2];
    const __half* Bg[2];
    #pragma unroll
    for (int i = 0; i < 2; i++) {
        Ag[i] = A  + (bRow + rowL[i]) * (long long)KTOT + cL[i] * 8;
        Bg[i] = Bt + (bCol + rowL[i]) * (long long)KTOT + cL[i] * 8;
    }

    float acc[4][4][4];
    #pragma unroll
    for (int mt = 0; mt < 4; mt++)
        #pragma unroll
        for (int nt = 0; nt < 4; nt++)
            #pragma unroll
            for (int q = 0; q < 4; q++) acc[mt][nt][q] = 0.f;

    #pragma unroll
    for (int s = 0; s < 2; s++) {
        #pragma unroll
        for (int i = 0; i < 2; i++) {
            cp16(aD[i] + (uint32_t)(s * OP_HALVES * 2), Ag[i] + s * BKH);
            cp16(bD[i] + (uint32_t)(s * OP_HALVES * 2), Bg[i] + s * BKH);
        }
        cp_commit();
    }

    for (int kt = 0; kt < KSTEPS; kt++) {
        cp_wait1();
        __syncthreads();

        if (kt + 2 < KSTEPS) {
            const int st = (kt + 2) % STG;
            #pragma unroll
            for (int i = 0; i < 2; i++) {
                cp16(aD[i] + (uint32_t)(st * OP_HALVES * 2), Ag[i] + (kt + 2) * BKH);
                cp16(bD[i] + (uint32_t)(st * OP_HALVES * 2), Bg[i] + (kt + 2) * BKH);
            }
        }
        cp_commit();

        const __half* Ab = Abase + (kt % STG) * OP_HALVES;
        const __half* Bb = Bbase + (kt % STG) * OP_HALVES;

        #pragma unroll
        for (int kk = 0; kk < BKH; kk += 16) {
            uint32_t af[4][4], bf[4][2];
            #pragma unroll
            for (int mt = 0; mt < 4; mt++) {
                int row = wm * 64 + mt * 16 + g;
                af[mt][0] = *(const uint32_t*)(Ab + row * STRH + kk + 2 * t);
                af[mt][1] = *(const uint32_t*)(Ab + (row + 8) * STRH + kk + 2 * t);
                af[mt][2] = *(const uint32_t*)(Ab + row * STRH + kk + 2 * t + 8);
                af[mt][3] = *(const uint32_t*)(Ab + (row + 8) * STRH + kk + 2 * t + 8);
            }
            #pragma unroll
            for (int nt = 0; nt < 4; nt++) {
                int col = wn * 32 + nt * 8 + g;
                bf[nt][0] = *(const uint32_t*)(Bb + col * STRH + kk + 2 * t);
                bf[nt][1] = *(const uint32_t*)(Bb + col * STRH + kk + 2 * t + 8);
            }
            #pragma unroll
            for (int mt = 0; mt < 4; mt++)
                #pragma unroll
                for (int nt = 0; nt < 4; nt++)
                    mma_f16(acc[mt][nt][0], acc[mt][nt][1], acc[mt][nt][2], acc[mt][nt][3],
                            af[mt][0], af[mt][1], af[mt][2], af[mt][3],
                            bf[nt][0], bf[nt][1]);
        }
        __syncthreads();
    }

    #pragma unroll
    for (int mt = 0; mt < 4; mt++) {
        #pragma unroll
        for (int nt = 0; nt < 4; nt++) {
            long long row0 = bRow + wm * 64 + mt * 16 + g;
            long long col  = bCol + wn * 32 + nt * 8 + t * 2;
            float b0 = 0.f, b1 = 0.f;
            if (bias) { b0 = bias[col]; b1 = bias[col + 1]; }
            float v00 = acc[mt][nt][0] + b0, v01 = acc[mt][nt][1] + b1;
            float v10 = acc[mt][nt][2] + b0, v11 = acc[mt][nt][3] + b1;
            if (halfOut) {
                __half2* C = (__half2*)Cout;
                C[(row0 * N + col) >> 1]       = __floats2half2_rn(v00, v01);
                C[((row0 + 8) * N + col) >> 1] = __floats2half2_rn(v10, v11);
            } else {
                float* C = (float*)Cout;
                *(float2*)(C + row0 * N + col)       = make_float2(v00, v01);
                *(float2*)(C + (row0 + 8) * N + col) = make_float2(v10, v11);
            }
        }
    }
}

// ---------------- edge attention (batched over positions, fp16 inputs) ------
__global__ void k_edge(const __half* __restrict__ QKV,
                       const int* __restrict__ src, const int* __restrict__ dst,
                       const __half* __restrict__ EwEb, int sStride,
                       const float* __restrict__ aw, __half* __restrict__ e_out) {
    long long w = ((long long)blockIdx.x * blockDim.x + threadIdx.x) >> 5;
    int lane = threadIdx.x & 31;
    if (w >= (long long)SQ * ET * NH) return;
    int s = (int)(w / (ET * NH));
    int r = (int)(w % (ET * NH));
    int e = r >> 2, h = r & 3;
    int sn = src[e], dn = dst[e];
    const __half* qp  = QKV + ((size_t)s * NN + dn) * (3 * DIM) + h * DH;
    const __half* kp  = QKV + ((size_t)s * NN + sn) * (3 * DIM) + DIM + h * DH;
    const __half* ewp = EwEb + ((size_t)s * sStride + e) * (2 * DIM) + h * 256;
    float lg = 0.f;
    float vals[4];
    #pragma unroll
    for (int i = 0; i < 4; i++) {
        int dd = lane + 32 * i;
        float tv = (__half2float(kp[dd]) + __half2float(qp[dd])) * __half2float(ewp[dd]);
        float ss = (tv >= 0.f) ? sqrtf(tv) : -sqrtf(-tv);   // signed sqrt
        ss = fmaxf(ss + __half2float(ewp[128 + dd]), 0.f);
        vals[i] = ss;
        lg = fmaf(ss, aw[h * DH + dd], lg);
    }
    if (e_out) {
        __half* op = e_out + ((size_t)s * ET + e) * DIM + h * DH;
        #pragma unroll
        for (int i = 0; i < 4; i++) op[lane + 32 * i] = __float2half_rn(vals[i]);
    }
    #pragma unroll
    for (int off = 16; off; off >>= 1) lg += __shfl_xor_sync(0xffffffffu, lg, off);
    if (lane == 0) g_logits[(size_t)s * ET * NH + e * NH + h] = lg;
}

__global__ void k_initmz() {
    int i = blockIdx.x * blockDim.x + threadIdx.x;
    if (i < SQ * NN * NH) { g_m[i] = __int_as_float(0xff800000); g_z[i] = 0.f; }
}

__device__ __forceinline__ void atomicMaxF(float* addr, float val) {
    int* ia = (int*)addr;
    int old = *ia;
    while (__int_as_float(old) < val) {
        int assumed = old;
        old = atomicCAS(ia, assumed, __float_as_int(val));
        if (old == assumed) break;
    }
}

__global__ void k_max(const int* __restrict__ dst) {
    int i = blockIdx.x * blockDim.x + threadIdx.x;
    if (i >= SQ * ET * NH) return;
    int s = i / (ET * NH);
    int r = i % (ET * NH);
    int e = r >> 2, h = r & 3;
    atomicMaxF(&g_m[(s * NN + dst[e]) * NH + h], g_logits[i]);
}

__global__ void k_expsum(const int* __restrict__ dst) {
    int i = blockIdx.x * blockDim.x + threadIdx.x;
    if (i >= SQ * ET * NH) return;
    int s = i / (ET * NH);
    int r = i % (ET * NH);
    int e = r >> 2, h = r & 3;
    float wv = expf(g_logits[i] - g_m[(s * NN + dst[e]) * NH + h]);
    g_logits[i] = wv;
    atomicAdd(&g_z[(s * NN + dst[e]) * NH + h], wv);
}

__global__ void k_msg(const __half* __restrict__ QKV, const int* __restrict__ src,
                      const int* __restrict__ dst, float* __restrict__ xout) {
    long long w = ((long long)blockIdx.x * blockDim.x + threadIdx.x) >> 5;
    int lane = threadIdx.x & 31;
    if (w >= (long long)SQ * ET * NH) return;
    int s = (int)(w / (ET * NH));
    int r = (int)(w % (ET * NH));
    int e = r >> 2, h = r & 3;
    int sn = src[e], dn = dst[e];
    float alpha = g_logits[(size_t)s * ET * NH + e * NH + h] /
                  (g_z[(s * NN + dn) * NH + h] + 1e-16f);
    const __half* vp = QKV + ((size_t)s * NN + sn) * (3 * DIM) + 2 * DIM + h * DH;
    float* op = xout + ((size_t)s * NN + dn) * DIM + h * DH;
    #pragma unroll
    for (int i = 0; i < 4; i++) {
        int dd = lane + 32 * i;
        atomicAdd(&op[dd], __half2float(vp[dd]) * alpha);
    }
}

// ---------------- host orchestration ---------------------------------------
extern "C" void kernel_launch(void* const* d_in, const int* in_sizes, int n_in,
                              void* d_out, int out_size) {
    const float* query   = (const float*)d_in[0];
    const int*   ei      = (const int*)  d_in[1];
    const int*   mapping = (const int*)  d_in[2];
    const float* emb     = (const float*)d_in[3];
    const float* wn_w1 = (const float*)d_in[5];
    const float* wn_b1 = (const float*)d_in[6];
    const float* wn_w2 = (const float*)d_in[7];
    const float* wn_b2 = (const float*)d_in[8];
    const float* wp_w1 = (const float*)d_in[9];
    const float* wp_b1 = (const float*)d_in[10];
    const float* wp_w2 = (const float*)d_in[11];
    const float* wp_b2 = (const float*)d_in[12];
    const float* WQ    = (const float*)d_in[13];
    const float* WK    = (const float*)d_in[14];
    const float* WV    = (const float*)d_in[15];
    const float* WE    = (const float*)d_in[16];
    const float* bE    = (const float*)d_in[17];
    const float* Aw    = (const float*)d_in[18];
    float* out = (float*)d_out;

    float  *node_raw, *node_pos, *Xout;
    __half *Xth, *Xh, *QKVh, *ehh, *e0h, *e1h, *Ew1h, *Ew2h;
    __half *Wpackth, *wn2th, *wp2th, *WEth;
    cudaGetSymbolAddress((void**)&node_raw, g_node_raw);
    cudaGetSymbolAddress((void**)&node_pos, g_node_pos);
    cudaGetSymbolAddress((void**)&Xth,  g_Xth);
    cudaGetSymbolAddress((void**)&Xh,   g_Xh);
    cudaGetSymbolAddress((void**)&Xout, g_Xout);
    cudaGetSymbolAddress((void**)&QKVh, g_QKVh);
    cudaGetSymbolAddress((void**)&ehh,  g_ehh);
    cudaGetSymbolAddress((void**)&e0h,  g_e0h);
    cudaGetSymbolAddress((void**)&e1h,  g_e1h);
    cudaGetSymbolAddress((void**)&Ew1h, g_Ew1h);
    cudaGetSymbolAddress((void**)&Ew2h, g_Ew2h);
    cudaGetSymbolAddress((void**)&Wpackth, g_Wpackth);
    cudaGetSymbolAddress((void**)&wn2th, g_wn2th);
    cudaGetSymbolAddress((void**)&wp2th, g_wp2th);
    cudaGetSymbolAddress((void**)&WEth,  g_WEth);

    cudaFuncSetAttribute(gemm_h, cudaFuncAttributeMaxDynamicSharedMemorySize, GEMM_SMEM);

    const int* srcp = ei;
    const int* dstp = ei + ET;
    const int T = 256;

    // ---- fp16 weight packs (tiny) ----
    k_transposeTh<<<(512 * 512) / T, T>>>(wn_w2, wn2th, 512);
    k_transposeTh<<<(512 * 512) / T, T>>>(wp_w2, wp2th, 512);
    k_transposeTh<<<(1024 * 512) / T, T>>>(WE, WEth, 1024);
    k_transposeTh<<<(1024 * 512) / T, T>>>(WE + 512 * 1024, WEth + 1024 * 512, 1024);
    k_packwTh<<<(2 * 1536 * 512) / T, T>>>(WQ, WK, WV);

    // ---- position-invariant precompute ----
    kzero<<<(NN * 8 + T - 1) / T, T>>>(node_raw, NN * 8);
    k_selfloop<<<(ET + T - 1) / T, T>>>(ei, emb);
    k_mlp1h<<<(NN * DIM) / T, T>>>(node_raw, wn_w1, wn_b1, Xth, NN);
    gemm_h<<<dim3(DIM / 128, NN / 128), T, GEMM_SMEM>>>(Xth, wn2th, wn_b2, node_pos,
                                                        NN, DIM, 0);
    k_mlp1h<<<(ET * DIM) / T, T>>>(emb, wp_w1, wp_b1, ehh, ET);
    gemm_h<<<dim3(DIM / 128, ET / 128), T, GEMM_SMEM>>>(ehh, wp2th, wp_b2, e0h,
                                                        ET, DIM, 1);
    gemm_h<<<dim3((2 * DIM) / 128, ET / 128), T, GEMM_SMEM>>>(e0h, WEth, bE, Ew1h,
                                                              ET, 2 * DIM, 1);

    // ---- batched positions ----
    k_add<<<(SQ * NN * DIM) / T, T>>>(query, node_pos, Xh);

    const long long edgeWarps = (long long)SQ * ET * NH;
    const int edgeWarpBlocks = (int)((edgeWarps * 32) / T);
    const int ehBlocks = (int)(edgeWarps / T);

    for (int l = 0; l < 2; l++) {
        const __half* EwEb;
        int sStride;
        if (l == 0) { EwEb = Ew1h; sStride = 0; }
        else {
            gemm_h<<<dim3((2 * DIM) / 128, (SQ * ET) / 128), T, GEMM_SMEM>>>(
                e1h, WEth + 1024 * 512, bE + 2 * DIM, Ew2h, SQ * ET, 2 * DIM, 1);
            EwEb = Ew2h; sStride = ET;
        }
        gemm_h<<<dim3((3 * DIM) / 128, (SQ * NN) / 128), T, GEMM_SMEM>>>(
            Xh, Wpackth + (size_t)l * 1536 * 512, nullptr, QKVh, SQ * NN, 3 * DIM, 1);

        k_edge<<<edgeWarpBlocks, T>>>(QKVh, srcp, dstp, EwEb, sStride, Aw + l * DIM,
                                      (l == 0) ? e1h : (__half*)nullptr);
        k_initmz<<<(SQ * NN * NH + T - 1) / T, T>>>();
        k_max<<<ehBlocks, T>>>(dstp);
        k_expsum<<<ehBlocks, T>>>(dstp);
        kzero<<<((size_t)SQ * NN * DIM + T - 1) / T, T>>>(Xout, (size_t)SQ * NN * DIM);
        k_msg<<<edgeWarpBlocks, T>>>(QKVh, srcp, dstp, Xout);
        if (l == 0)
            k_tohalf<<<((size_t)SQ * NN * DIM + T - 1) / T, T>>>(Xout, Xh,
                                                                 (size_t)SQ * NN * DIM);
    }
    k_gather<<<(BOUT * SQ * DIM) / T, T>>>(Xout, mapping, out);
}

// round 8
// speedup vs baseline: 1.6313x; 1.1781x over previous
#include <cuda_runtime.h>
#include <cuda_fp16.h>
#include <math.h>
#include <stdint.h>

#define NN   8192
#define SQ   4
#define DIM  512
#define NH   4
#define DH   128
#define ET   73728
#define BOUT 128

// ---------------- scratch (device globals; no runtime alloc allowed) -------
__device__ float  g_node_raw[NN * 8];
__device__ float  g_node_pos[NN * DIM];
__device__ __half g_Xth[NN * DIM];                   // node mlp hidden (fp16)
__device__ __half g_Xh [(size_t)SQ * NN * DIM];      // layer input x (fp16)
__device__ float  g_Xout[(size_t)SQ * NN * DIM];     // attention out (fp32 atomics)
__device__ __half g_QKVh[(size_t)SQ * NN * 3 * DIM]; // fused QKV (fp16)
__device__ __half g_ehh [(size_t)ET * DIM];          // edge MLP hidden (fp16)
__device__ __half g_e0h [(size_t)ET * DIM];          // e0 (fp16)
__device__ __half g_e1h [(size_t)SQ * ET * DIM];     // layer-0 e_out (fp16)
__device__ __half g_Ew1h[(size_t)ET * 2 * DIM];      // layer-0 Ew/Eb (fp16)
__device__ __half g_Ew2h[(size_t)SQ * ET * 2 * DIM]; // layer-1 Ew/Eb (fp16)
__device__ float  g_logits[SQ * ET * NH];
__device__ float  g_m[SQ * NN * NH];
__device__ float  g_z[SQ * NN * NH];
// K-major (N,K) fp16 weights
__device__ __half g_Wpackth[2 * 3 * DIM * DIM];      // [l][n=1536][k=512]
__device__ __half g_wn2th[DIM * DIM];
__device__ __half g_wp2th[DIM * DIM];
__device__ __half g_WEth[2 * 2 * DIM * DIM];         // [l][n=1024][k=512]

// ---------------- small utility kernels ------------------------------------
__global__ void kzero(float* __restrict__ p, size_t n) {
    size_t i = (size_t)blockIdx.x * blockDim.x + threadIdx.x;
    if (i < n) p[i] = 0.f;
}

__global__ void k_tohalf(const float* __restrict__ s, __half* __restrict__ d, size_t n) {
    size_t i = (size_t)blockIdx.x * blockDim.x + threadIdx.x;
    if (i < n) d[i] = __float2half_rn(s[i]);
}

__global__ void k_selfloop(const int* __restrict__ ei, const float* __restrict__ emb) {
    int e = blockIdx.x * blockDim.x + threadIdx.x;
    if (e >= ET) return;
    int s = ei[e], d = ei[ET + e];
    if (s == d) {
        #pragma unroll
        for (int r = 0; r < 8; r++)
            atomicAdd(&g_node_raw[s * 8 + r], emb[e * 8 + r]);
    }
}

// out[n,j] = fp16( relu( sum_r in[n,r]*w1[r,j] + b1[j] ) )
__global__ void k_mlp1h(const float* __restrict__ in, const float* __restrict__ w1,
                        const float* __restrict__ b1, __half* __restrict__ out, int rows) {
    long long idx = (long long)blockIdx.x * blockDim.x + threadIdx.x;
    if (idx >= (long long)rows * DIM) return;
    int n = (int)(idx >> 9), j = (int)(idx & 511);
    const float* ip = in + (long long)n * 8;
    float acc = b1[j];
    #pragma unroll
    for (int r = 0; r < 8; r++) acc = fmaf(ip[r], w1[r * DIM + j], acc);
    out[idx] = __float2half_rn(fmaxf(acc, 0.f));
}

// Xh[s][n][j] = fp16( query[n][s][j] + node_pos[n][j] )
__global__ void k_add(const float* __restrict__ query, const float* __restrict__ npos,
                      __half* __restrict__ X) {
    size_t idx = (size_t)blockIdx.x * blockDim.x + threadIdx.x;
    if (idx >= (size_t)SQ * NN * DIM) return;
    int j = (int)(idx & 511);
    int n = (int)((idx >> 9) % NN);
    int s = (int)(idx / ((size_t)NN * DIM));
    X[idx] = __float2half_rn(query[(size_t)n * SQ * DIM + (size_t)s * DIM + j] +
                             npos[(size_t)n * DIM + j]);
}

__global__ void k_gather(const float* __restrict__ X, const int* __restrict__ mapping,
                         float* __restrict__ out) {
    int idx = blockIdx.x * blockDim.x + threadIdx.x;
    if (idx >= BOUT * SQ * DIM) return;
    int j = idx & 511;
    int s = (idx >> 9) & 3;
    int b = idx >> 11;
    out[idx] = X[((size_t)s * NN + mapping[b]) * DIM + j];
}

// transpose + fp16: W[512][Nw] -> Wt[Nw][512]
__global__ void k_transposeTh(const float* __restrict__ W, __half* __restrict__ Wt, int Nw) {
    int idx = blockIdx.x * blockDim.x + threadIdx.x;
    if (idx >= Nw * 512) return;
    int k = idx & 511;
    int n = idx >> 9;
    Wt[idx] = __float2half_rn(W[(size_t)k * Nw + n]);
}

// fused QKV pack, transposed: Wpackth[l][n(1536)][k(512)]
__global__ void k_packwTh(const float* __restrict__ WQ, const float* __restrict__ WK,
                          const float* __restrict__ WV) {
    int idx = blockIdx.x * blockDim.x + threadIdx.x;
    if (idx >= 2 * 1536 * 512) return;
    int k = idx & 511;
    int n = (idx >> 9) % 1536;
    int l = idx / (1536 * 512);
    const float* W = (n < 512) ? WQ : ((n < 1024) ? WK : WV);
    int nn = n & 511;
    g_Wpackth[idx] = __float2half_rn(W[(size_t)l * 512 * 512 + (size_t)k * 512 + nn]);
}

// ---------------- fp16 tensor-core GEMM (ldmatrix fragments) ----------------
// C[M,N] = A[M,512] @ Bt[N,512]^T (+bias). A,Bt fp16, K-major. M,N mult of 128.
#define BKH     32
#define KTOT    512
#define KSTEPS  (KTOT / BKH)          // 16
#define STG     3
#define STRH    40                    // halves per smem row (80B, LDSM conflict-free)
#define OP_HALVES (128 * STRH)
#define GEMM_SMEM (STG * 2 * OP_HALVES * 2)

__device__ __forceinline__ void cp16(uint32_t dst, const void* src) {
    asm volatile("cp.async.cg.shared.global [%0], [%1], 16;\n" :: "r"(dst), "l"(src));
}
__device__ __forceinline__ void cp_commit() { asm volatile("cp.async.commit_group;\n"); }
__device__ __forceinline__ void cp_wait1()  { asm volatile("cp.async.wait_group 1;\n"); }

__device__ __forceinline__ void ldsm4(uint32_t& r0, uint32_t& r1, uint32_t& r2,
                                      uint32_t& r3, uint32_t addr) {
    asm volatile("ldmatrix.sync.aligned.m8n8.x4.shared.b16 {%0,%1,%2,%3}, [%4];"
                 : "=r"(r0), "=r"(r1), "=r"(r2), "=r"(r3) : "r"(addr));
}

__device__ __forceinline__ void mma_f16(float& c0, float& c1, float& c2, float& c3,
                                        uint32_t a0, uint32_t a1, uint32_t a2, uint32_t a3,
                                        uint32_t b0, uint32_t b1) {
    asm volatile("mma.sync.aligned.m16n8k16.row.col.f32.f16.f16.f32 "
                 "{%0,%1,%2,%3}, {%4,%5,%6,%7}, {%8,%9}, {%0,%1,%2,%3};\n"
                 : "+f"(c0), "+f"(c1), "+f"(c2), "+f"(c3)
                 : "r"(a0), "r"(a1), "r"(a2), "r"(a3), "r"(b0), "r"(b1));
}

__global__ void __launch_bounds__(256, 2)
gemm_h(const __half* __restrict__ A, const __half* __restrict__ Bt,
       const float* __restrict__ bias, void* __restrict__ Cout,
       int M, int N, int halfOut) {
    extern __shared__ __half sh[];
    __half* Abase = sh;
    __half* Bbase = sh + STG * OP_HALVES;

    const int tid  = threadIdx.x;
    const int lane = tid & 31;
    const int warp = tid >> 5;
    const int wm = warp & 1;      // 2 warps along M (64 rows)
    const int wn = warp >> 1;     // 4 warps along N (32 cols)
    const int g  = lane >> 2;
    const int t  = lane & 3;

    const long long bRow = (long long)blockIdx.y * 128;
    const long long bCol = (long long)blockIdx.x * 128;

    // cp.async loader mapping
    int rowL[2], cL[2];
    #pragma unroll
    for (int i = 0; i < 2; i++) {
        int ch = tid * 2 + i;
        rowL[i] = ch >> 2;
        cL[i]   = ch & 3;
    }
    const uint32_t suA = (uint32_t)__cvta_generic_to_shared(Abase);
    const uint32_t suB = (uint32_t)__cvta_generic_to_shared(Bbase);
    uint32_t aD[2], bD[2];
    #pragma unroll
    for (int i = 0; i < 2; i++) {
        aD[i] = suA + (uint32_t)(rowL[i] * STRH + cL[i] * 8) * 2u;
        bD[i] = suB + (uint32_t)(rowL[i] * STRH + cL[i] * 8) * 2u;
    }
    const __half* Ag[2];
    const __half* Bg[2];
    #pragma unroll
    for (int i = 0; i < 2; i++) {
        Ag[i] = A  + (bRow + rowL[i]) * (long long)KTOT + cL[i] * 8;
        Bg[i] = Bt + (bCol + rowL[i]) * (long long)KTOT + cL[i] * 8;
    }

    // ldmatrix lane offsets (in halves)
    const uint32_t laneAoff = (uint32_t)(((lane & 7) + ((lane >> 3) & 1) * 8) * STRH
                                         + (lane >> 4) * 8);
    const uint32_t laneBoff = (uint32_t)(((lane & 7) + (lane >> 4) * 8) * STRH
                                         + ((lane >> 3) & 1) * 8);

    float acc[4][4][4];
    #pragma unroll
    for (int mt = 0; mt < 4; mt++)
        #pragma unroll
        for (int nt = 0; nt < 4; nt++)
            #pragma unroll
            for (int q = 0; q < 4; q++) acc[mt][nt][q] = 0.f;

    #pragma unroll
    for (int s = 0; s < 2; s++) {
        #pragma unroll
        for (int i = 0; i < 2; i++) {
            cp16(aD[i] + (uint32_t)(s * OP_HALVES * 2), Ag[i] + s * BKH);
            cp16(bD[i] + (uint32_t)(s * OP_HALVES * 2), Bg[i] + s * BKH);
        }
        cp_commit();
    }

    for (int kt = 0; kt < KSTEPS; kt++) {
        cp_wait1();
        __syncthreads();

        if (kt + 2 < KSTEPS) {
            const int st = (kt + 2) % STG;
            #pragma unroll
            for (int i = 0; i < 2; i++) {
                cp16(aD[i] + (uint32_t)(st * OP_HALVES * 2), Ag[i] + (kt + 2) * BKH);
                cp16(bD[i] + (uint32_t)(st * OP_HALVES * 2), Bg[i] + (kt + 2) * BKH);
            }
        }
        cp_commit();

        const uint32_t Ab = suA + (uint32_t)((kt % STG) * OP_HALVES) * 2u;
        const uint32_t Bb = suB + (uint32_t)((kt % STG) * OP_HALVES) * 2u;

        #pragma unroll
        for (int kk = 0; kk < BKH; kk += 16) {
            uint32_t af[4][4], bf[4][2];
            #pragma unroll
            for (int mt = 0; mt < 4; mt++) {
                uint32_t addr = Ab + 2u * (laneAoff + (uint32_t)((wm * 64 + mt * 16) * STRH + kk));
                ldsm4(af[mt][0], af[mt][1], af[mt][2], af[mt][3], addr);
            }
            #pragma unroll
            for (int p = 0; p < 2; p++) {
                uint32_t addr = Bb + 2u * (laneBoff + (uint32_t)((wn * 32 + p * 16) * STRH + kk));
                ldsm4(bf[2 * p][0], bf[2 * p][1], bf[2 * p + 1][0], bf[2 * p + 1][1], addr);
            }
            #pragma unroll
            for (int mt = 0; mt < 4; mt++)
                #pragma unroll
                for (int nt = 0; nt < 4; nt++)
                    mma_f16(acc[mt][nt][0], acc[mt][nt][1], acc[mt][nt][2], acc[mt][nt][3],
                            af[mt][0], af[mt][1], af[mt][2], af[mt][3],
                            bf[nt][0], bf[nt][1]);
        }
        __syncthreads();
    }

    #pragma unroll
    for (int mt = 0; mt < 4; mt++) {
        #pragma unroll
        for (int nt = 0; nt < 4; nt++) {
            long long row0 = bRow + wm * 64 + mt * 16 + g;
            long long col  = bCol + wn * 32 + nt * 8 + t * 2;
            float b0 = 0.f, b1 = 0.f;
            if (bias) { b0 = bias[col]; b1 = bias[col + 1]; }
            float v00 = acc[mt][nt][0] + b0, v01 = acc[mt][nt][1] + b1;
            float v10 = acc[mt][nt][2] + b0, v11 = acc[mt][nt][3] + b1;
            if (halfOut) {
                __half2* C = (__half2*)Cout;
                C[(row0 * N + col) >> 1]       = __floats2half2_rn(v00, v01);
                C[((row0 + 8) * N + col) >> 1] = __floats2half2_rn(v10, v11);
            } else {
                float* C = (float*)Cout;
                *(float2*)(C + row0 * N + col)       = make_float2(v00, v01);
                *(float2*)(C + (row0 + 8) * N + col) = make_float2(v10, v11);
            }
        }
    }
}

// ---------------- edge attention (batched over positions, half2) ------------
__global__ void k_edge(const __half* __restrict__ QKV,
                       const int* __restrict__ src, const int* __restrict__ dst,
                       const __half* __restrict__ EwEb, int sStride,
                       const float* __restrict__ aw, __half* __restrict__ e_out) {
    long long w = ((long long)blockIdx.x * blockDim.x + threadIdx.x) >> 5;
    int lane = threadIdx.x & 31;
    if (w >= (long long)SQ * ET * NH) return;
    int s = (int)(w / (ET * NH));
    int r = (int)(w % (ET * NH));
    int e = r >> 2, h = r & 3;
    int sn = src[e], dn = dst[e];
    const __half2* qp  = (const __half2*)(QKV + ((size_t)s * NN + dn) * (3 * DIM) + h * DH);
    const __half2* kp  = (const __half2*)(QKV + ((size_t)s * NN + sn) * (3 * DIM) + DIM + h * DH);
    const __half2* ewp = (const __half2*)(EwEb + ((size_t)s * sStride + e) * (2 * DIM) + h * 256);
    float lg = 0.f;
    float2 vals[2];
    #pragma unroll
    for (int i = 0; i < 2; i++) {
        int dd = lane + 32 * i;               // half2 index, 0..63
        float2 kq = __half22float2(__hadd2(kp[dd], qp[dd]));
        float2 ew = __half22float2(ewp[dd]);
        float2 eb = __half22float2(ewp[dd + 64]);
        float t0 = kq.x * ew.x, t1 = kq.y * ew.y;
        float s0 = (t0 >= 0.f) ? sqrtf(t0) : -sqrtf(-t0);
        float s1 = (t1 >= 0.f) ? sqrtf(t1) : -sqrtf(-t1);
        s0 = fmaxf(s0 + eb.x, 0.f);
        s1 = fmaxf(s1 + eb.y, 0.f);
        vals[i] = make_float2(s0, s1);
        lg = fmaf(s0, aw[h * DH + 2 * dd], lg);
        lg = fmaf(s1, aw[h * DH + 2 * dd + 1], lg);
    }
    if (e_out) {
        __half2* op = (__half2*)(e_out + ((size_t)s * ET + e) * DIM + h * DH);
        #pragma unroll
        for (int i = 0; i < 2; i++)
            op[lane + 32 * i] = __floats2half2_rn(vals[i].x, vals[i].y);
    }
    #pragma unroll
    for (int off = 16; off; off >>= 1) lg += __shfl_xor_sync(0xffffffffu, lg, off);
    if (lane == 0) g_logits[(size_t)s * ET * NH + e * NH + h] = lg;
}

__global__ void k_initmz() {
    int i = blockIdx.x * blockDim.x + threadIdx.x;
    if (i < SQ * NN * NH) { g_m[i] = __int_as_float(0xff800000); g_z[i] = 0.f; }
}

__device__ __forceinline__ void atomicMaxF(float* addr, float val) {
    int* ia = (int*)addr;
    int old = *ia;
    while (__int_as_float(old) < val) {
        int assumed = old;
        old = atomicCAS(ia, assumed, __float_as_int(val));
        if (old == assumed) break;
    }
}

__global__ void k_max(const int* __restrict__ dst) {
    int i = blockIdx.x * blockDim.x + threadIdx.x;
    if (i >= SQ * ET * NH) return;
    int s = i / (ET * NH);
    int r = i % (ET * NH);
    int e = r >> 2, h = r & 3;
    atomicMaxF(&g_m[(s * NN + dst[e]) * NH + h], g_logits[i]);
}

__global__ void k_expsum(const int* __restrict__ dst) {
    int i = blockIdx.x * blockDim.x + threadIdx.x;
    if (i >= SQ * ET * NH) return;
    int s = i / (ET * NH);
    int r = i % (ET * NH);
    int e = r >> 2, h = r & 3;
    float wv = expf(g_logits[i] - g_m[(s * NN + dst[e]) * NH + h]);
    g_logits[i] = wv;
    atomicAdd(&g_z[(s * NN + dst[e]) * NH + h], wv);
}

__global__ void k_msg(const __half* __restrict__ QKV, const int* __restrict__ src,
                      const int* __restrict__ dst, float* __restrict__ xout) {
    long long w = ((long long)blockIdx.x * blockDim.x + threadIdx.x) >> 5;
    int lane = threadIdx.x & 31;
    if (w >= (long long)SQ * ET * NH) return;
    int s = (int)(w / (ET * NH));
    int r = (int)(w % (ET * NH));
    int e = r >> 2, h = r & 3;
    int sn = src[e], dn = dst[e];
    float alpha = g_logits[(size_t)s * ET * NH + e * NH + h] /
                  (g_z[(s * NN + dn) * NH + h] + 1e-16f);
    const __half2* vp = (const __half2*)(QKV + ((size_t)s * NN + sn) * (3 * DIM)
                                         + 2 * DIM + h * DH);
    float* op = xout + ((size_t)s * NN + dn) * DIM + h * DH;
    #pragma unroll
    for (int i = 0; i < 2; i++) {
        int dd = lane + 32 * i;
        float2 v = __half22float2(vp[dd]);
        atomicAdd(&op[2 * dd],     v.x * alpha);
        atomicAdd(&op[2 * dd + 1], v.y * alpha);
    }
}

// ---------------- host orchestration ---------------------------------------
extern "C" void kernel_launch(void* const* d_in, const int* in_sizes, int n_in,
                              void* d_out, int out_size) {
    const float* query   = (const float*)d_in[0];
    const int*   ei      = (const int*)  d_in[1];
    const int*   mapping = (const int*)  d_in[2];
    const float* emb     = (const float*)d_in[3];
    const float* wn_w1 = (const float*)d_in[5];
    const float* wn_b1 = (const float*)d_in[6];
    const float* wn_w2 = (const float*)d_in[7];
    const float* wn_b2 = (const float*)d_in[8];
    const float* wp_w1 = (const float*)d_in[9];
    const float* wp_b1 = (const float*)d_in[10];
    const float* wp_w2 = (const float*)d_in[11];
    const float* wp_b2 = (const float*)d_in[12];
    const float* WQ    = (const float*)d_in[13];
    const float* WK    = (const float*)d_in[14];
    const float* WV    = (const float*)d_in[15];
    const float* WE    = (const float*)d_in[16];
    const float* bE    = (const float*)d_in[17];
    const float* Aw    = (const float*)d_in[18];
    float* out = (float*)d_out;

    float  *node_raw, *node_pos, *Xout;
    __half *Xth, *Xh, *QKVh, *ehh, *e0h, *e1h, *Ew1h, *Ew2h;
    __half *Wpackth, *wn2th, *wp2th, *WEth;
    cudaGetSymbolAddress((void**)&node_raw, g_node_raw);
    cudaGetSymbolAddress((void**)&node_pos, g_node_pos);
    cudaGetSymbolAddress((void**)&Xth,  g_Xth);
    cudaGetSymbolAddress((void**)&Xh,   g_Xh);
    cudaGetSymbolAddress((void**)&Xout, g_Xout);
    cudaGetSymbolAddress((void**)&QKVh, g_QKVh);
    cudaGetSymbolAddress((void**)&ehh,  g_ehh);
    cudaGetSymbolAddress((void**)&e0h,  g_e0h);
    cudaGetSymbolAddress((void**)&e1h,  g_e1h);
    cudaGetSymbolAddress((void**)&Ew1h, g_Ew1h);
    cudaGetSymbolAddress((void**)&Ew2h, g_Ew2h);
    cudaGetSymbolAddress((void**)&Wpackth, g_Wpackth);
    cudaGetSymbolAddress((void**)&wn2th, g_wn2th);
    cudaGetSymbolAddress((void**)&wp2th, g_wp2th);
    cudaGetSymbolAddress((void**)&WEth,  g_WEth);

    cudaFuncSetAttribute(gemm_h, cudaFuncAttributeMaxDynamicSharedMemorySize, GEMM_SMEM);

    const int* srcp = ei;
    const int* dstp = ei + ET;
    const int T = 256;

    // ---- fp16 weight packs (tiny) ----
    k_transposeTh<<<(512 * 512) / T, T>>>(wn_w2, wn2th, 512);
    k_transposeTh<<<(512 * 512) / T, T>>>(wp_w2, wp2th, 512);
    k_transposeTh<<<(1024 * 512) / T, T>>>(WE, WEth, 1024);
    k_transposeTh<<<(1024 * 512) / T, T>>>(WE + 512 * 1024, WEth + 1024 * 512, 1024);
    k_packwTh<<<(2 * 1536 * 512) / T, T>>>(WQ, WK, WV);

    // ---- position-invariant precompute ----
    kzero<<<(NN * 8 + T - 1) / T, T>>>(node_raw, NN * 8);
    k_selfloop<<<(ET + T - 1) / T, T>>>(ei, emb);
    k_mlp1h<<<(NN * DIM) / T, T>>>(node_raw, wn_w1, wn_b1, Xth, NN);
    gemm_h<<<dim3(DIM / 128, NN / 128), T, GEMM_SMEM>>>(Xth, wn2th, wn_b2, node_pos,
                                                        NN, DIM, 0);
    k_mlp1h<<<(ET * DIM) / T, T>>>(emb, wp_w1, wp_b1, ehh, ET);
    gemm_h<<<dim3(DIM / 128, ET / 128), T, GEMM_SMEM>>>(ehh, wp2th, wp_b2, e0h,
                                                        ET, DIM, 1);
    gemm_h<<<dim3((2 * DIM) / 128, ET / 128), T, GEMM_SMEM>>>(e0h, WEth, bE, Ew1h,
                                                              ET, 2 * DIM, 1);

    // ---- batched positions ----
    k_add<<<(SQ * NN * DIM) / T, T>>>(query, node_pos, Xh);

    const long long edgeWarps = (long long)SQ * ET * NH;
    const int edgeWarpBlocks = (int)((edgeWarps * 32) / T);
    const int ehBlocks = (int)(edgeWarps / T);

    for (int l = 0; l < 2; l++) {
        const __half* EwEb;
        int sStride;
        if (l == 0) { EwEb = Ew1h; sStride = 0; }
        else {
            gemm_h<<<dim3((2 * DIM) / 128, (SQ * ET) / 128), T, GEMM_SMEM>>>(
                e1h, WEth + 1024 * 512, bE + 2 * DIM, Ew2h, SQ * ET, 2 * DIM, 1);
            EwEb = Ew2h; sStride = ET;
        }
        gemm_h<<<dim3((3 * DIM) / 128, (SQ * NN) / 128), T, GEMM_SMEM>>>(
            Xh, Wpackth + (size_t)l * 1536 * 512, nullptr, QKVh, SQ * NN, 3 * DIM, 1);

        k_edge<<<edgeWarpBlocks, T>>>(QKVh, srcp, dstp, EwEb, sStride, Aw + l * DIM,
                                      (l == 0) ? e1h : (__half*)nullptr);
        k_initmz<<<(SQ * NN * NH + T - 1) / T, T>>>();
        k_max<<<ehBlocks, T>>>(dstp);
        k_expsum<<<ehBlocks, T>>>(dstp);
        kzero<<<((size_t)SQ * NN * DIM + T - 1) / T, T>>>(Xout, (size_t)SQ * NN * DIM);
        k_msg<<<edgeWarpBlocks, T>>>(QKVh, srcp, dstp, Xout);
        if (l == 0)
            k_tohalf<<<((size_t)SQ * NN * DIM + T - 1) / T, T>>>(Xout, Xh,
                                                                 (size_t)SQ * NN * DIM);
    }
    k_gather<<<(BOUT * SQ * DIM) / T, T>>>(Xout, mapping, out);
}